// round 12
// baseline (speedup 1.0000x reference)
#include <cuda_runtime.h>
#include <cstdint>

// LBP semantic dependency, difference-space, ratio-space state X = 2^(-d).
// 6-CTA cluster per (i,b): rank -> (type t=r>>1, parity c=r&1).
// Pv = 2^(p*log2e) computed on it=0 from raw p and persisted to gmem scratch
// (L2-hot on it=1,2). Rowsums via smem atomics (R10). Cluster Δb exchange via
// per-thread red.relaxed.cluster + mbarrier arrive/try_wait (NOT a full
// cluster barrier); DSMEM latency hidden under next-iter X staging.

#define S    160
#define S2   25600
#define S3   4096000
#define DP   81          /* X pitch */
#define NTH  512
#define LOG2E 1.4426950408889634f

/* shared layout (floats) */
#define OFF_X    0                    /* X[160][81] = 12960 */
#define OFF_DB   12960
#define OFF_SE   13120
#define OFF_W    13280
#define OFF_MJ   13440
#define OFF_RS   13600
#define OFF_ACC  13760                /* [2][160] */
#define OFF_EX   14080
#define OFF_MBAR 14240                /* 8-byte mbarrier (2 float slots) */
#define SMEM_FLOATS (OFF_MBAR + 2)
#define SMEM_BYTES  (SMEM_FLOATS * 4)

#define MBAR_EXPECT 800               /* 5 peers x 160 threads */

/* global scratch for Pv: [b][i][rank][k(160)][jh(80)] = 98.3 MB */
__device__ float P2g[2 * 160 * 6 * 160 * 80];

extern __shared__ float sm[];

__device__ __forceinline__ uint32_t smem_u32(const void* p) {
    uint32_t a;
    asm("{ .reg .u64 t; cvta.to.shared.u64 t, %1; cvt.u32.u64 %0, t; }"
        : "=r"(a) : "l"(p));
    return a;
}
__device__ __forceinline__ void cluster_sync_() {
    asm volatile("barrier.cluster.arrive.aligned;" ::: "memory");
    asm volatile("barrier.cluster.wait.aligned;" ::: "memory");
}
__device__ __forceinline__ void red_remote_add_f32(uint32_t laddr, uint32_t rank, float v) {
    asm volatile(
        "{ .reg .b32 r; mapa.shared::cluster.u32 r, %0, %1; "
        "red.relaxed.cluster.shared::cluster.add.f32 [r], %2; }"
        :: "r"(laddr), "r"(rank), "f"(v) : "memory");
}
__device__ __forceinline__ void mbar_remote_arrive(uint32_t mbarAddr, uint32_t rank) {
    asm volatile(
        "{ .reg .b32 r; mapa.shared::cluster.u32 r, %0, %1; "
        "mbarrier.arrive.release.cluster.shared::cluster.b64 _, [r]; }"
        :: "r"(mbarAddr), "r"(rank) : "memory");
}
__device__ __forceinline__ void mbar_wait_parity(uint32_t mbarAddr, uint32_t parity) {
    asm volatile(
        "{\n\t"
        ".reg .pred P;\n\t"
        "WL_%=:\n\t"
        "mbarrier.try_wait.parity.acquire.cluster.shared::cta.b64 P, [%0], %1, 0x989680;\n\t"
        "@P bra WD_%=;\n\t"
        "bra WL_%=;\n\t"
        "WD_%=:\n\t"
        "}"
        :: "r"(mbarAddr), "r"(parity) : "memory");
}
__device__ __forceinline__ float ex2f_(float x) {
    float y; asm("ex2.approx.ftz.f32 %0, %1;" : "=f"(y) : "f"(x)); return y;
}
__device__ __forceinline__ float lg2f_(float x) {
    float y; asm("lg2.approx.ftz.f32 %0, %1;" : "=f"(y) : "f"(x)); return y;
}
__device__ __forceinline__ float rcpf_(float x) {
    float y; asm("rcp.approx.ftz.f32 %0, %1;" : "=f"(y) : "f"(x)); return y;
}
__device__ __forceinline__ bool mask_at(const void* m, bool byteMask, int idx) {
    if (byteMask) return ((const unsigned char*)m)[idx] != 0;
    return ((const uint32_t*)m)[idx] != 0u;
}

__global__ void __launch_bounds__(NTH, 3) __cluster_dims__(6, 1, 1)
lbp_kernel(const float* __restrict__ s_edge,
           const float* __restrict__ s_sib,
           const float* __restrict__ s_cop,
           const float* __restrict__ s_grd,
           const void* __restrict__ mask,
           float* __restrict__ out)
{
    const int tid  = threadIdx.x;
    const int bx   = blockIdx.x;
    const int rank = bx % 6;
    const int prob = bx / 6;
    const int i    = prob % S;
    const int b    = prob / S;
    const int t    = rank >> 1;      /* score type */
    const int c    = rank & 1;       /* pair-parity class */

    const int tr    = tid & 31;              /* lane: row group */
    const int tc    = tid >> 5;              /* warp: col group */
    const int par   = c ^ (tr & 1);          /* fixed column parity */
    const int kbase = 10 * tc + par;         /* k_s = kbase + 2s */

    const bool byteMask = (*(const uint32_t*)mask == 0x01010101u);

    float* __restrict__ X  = sm + OFF_X;
    float* __restrict__ DB = sm + OFF_DB;
    float* __restrict__ EX = sm + OFF_EX;

    const float* __restrict__ Praw =
        (t == 0 ? s_sib : (t == 1 ? s_cop : s_grd)) + (size_t)b * S3 + i * S;
    float* __restrict__ P2 = P2g + ((size_t)(b * S + i) * 6 + rank) * 12800;

    /* per-thread bases: raw p at [k][j], scratch at [k][jh] */
    const float* __restrict__ pb  = Praw + (size_t)kbase * S2 + tr;
    float*       __restrict__ p2b = P2 + kbase * 80 + (tr >> 1);

    /* ---- init scalars (X needs no init: it=0 writes every cell) ---- */
    if (tid < S) {
        const int k = tid;
        const bool mk = mask_at(mask, byteMask, b * S2 + k * S + i);
        sm[OFF_W  + k] = (mk && (k != i)) ? 1.f : 0.f;
        sm[OFF_MJ + k] = mk ? 1.f : 0.f;
        sm[OFF_SE + k] = s_edge[b * S2 + k * S + i] * LOG2E;
        DB[k] = 0.f;
        EX[k] = 1.f;
        sm[OFF_RS + k] = 0.f;
        sm[OFF_ACC + k] = 0.f;
        sm[OFF_ACC + S + k] = 0.f;
    }
    const uint32_t mbarAddr = smem_u32(sm + OFF_MBAR);
    if (tid == 0) {
        asm volatile("mbarrier.init.shared.b64 [%0], %1;"
                     :: "r"(mbarAddr), "r"((uint32_t)MBAR_EXPECT) : "memory");
    }
    __syncthreads();
    cluster_sync_();   /* all ranks' ACC + mbar initialized before remote ops */

    const uint32_t accAddr = smem_u32(sm + OFF_ACC);
    float dbFinal = 0.f;

    /* hoisted per-column weights (constant across iterations) */
    float Wreg[5];
    #pragma unroll
    for (int s = 0; s < 5; ++s) Wreg[s] = sm[OFF_W + kbase + 2 * s];

    float Xold[25];   /* transpose partners, staged at end of prev iteration */

    for (int it = 0; it < 3; ++it) {
        float acc[5];

        if (it == 0) {
            /* Xold = 1, E = 1 -> e = 1. Compute Pv from raw p; persist it. */
            #pragma unroll
            for (int r = 0; r < 5; ++r) {
                const int jv = tr + 32 * r;
                const int wrow = jv * DP + 5 * tc;
                float av = 0.f;
                #pragma unroll
                for (int s = 0; s < 5; ++s) {
                    const int k = kbase + 2 * s;
                    const float Pv = ex2f_(pb[(size_t)2 * s * S2 + 32 * r] * LOG2E);
                    p2b[160 * s + 16 * r] = Pv;
                    const float rr = 2.f * rcpf_(1.f + Pv);   /* 2^(-d_new) */
                    X[wrow + s] = rr;
                    const float dn = lg2f_(rr);               /* = -d_new */
                    const float wc = (k == jv) ? 0.f : Wreg[s];
                    av = fmaf(wc, dn, av);
                }
                acc[r] = av;
            }
        } else {
            float Ereg[5];
            #pragma unroll
            for (int s = 0; s < 5; ++s) Ereg[s] = EX[kbase + 2 * s];

            #pragma unroll
            for (int r = 0; r < 5; ++r) {
                const int jv = tr + 32 * r;
                const int wrow = jv * DP + 5 * tc;
                float av = 0.f;
                #pragma unroll
                for (int s = 0; s < 5; ++s) {
                    const int k  = kbase + 2 * s;
                    const float Pv = p2b[160 * s + 16 * r];   /* L2-hot */
                    const float e  = Ereg[s] * Xold[r * 5 + s];
                    const float num = fmaf(e, Pv, 1.f);
                    const float den = e + 1.f;
                    const float rr  = den * rcpf_(num);       /* 2^(-d_new) */
                    X[wrow + s] = rr;
                    const float dn  = lg2f_(rr);              /* = -d_new */
                    const float wc  = (k == jv) ? 0.f : Wreg[s];
                    av = fmaf(wc, dn, av);
                }
                acc[r] = av;
            }
        }

        #pragma unroll
        for (int r = 0; r < 5; ++r)
            atomicAdd(&sm[OFF_RS + tr + 32 * r], acc[r]);
        __syncthreads();   /* X writes + RS complete */

        /* ---- post partials to the 5 peers, then signal (per-thread order:
           red -> arrive.release guarantees visibility on acquire-wait) ---- */
        const int buf = it & 1;
        float myPart = 0.f;
        if (tid < S) {
            myPart = sm[OFF_RS + tid];
            const uint32_t dst = accAddr + 4u * (uint32_t)(buf * S + tid);
            #pragma unroll
            for (int r = 0; r < 6; ++r)
                if (r != rank) {
                    red_remote_add_f32(dst, (uint32_t)r, myPart);
                    mbar_remote_arrive(mbarAddr, (uint32_t)r);
                }
        }

        /* ---- stage next iteration's transpose partners (hides DSMEM) ---- */
        if (it < 2) {
            #pragma unroll
            for (int r = 0; r < 5; ++r) {
                const int rb = (tr >> 1) + 16 * r;
                #pragma unroll
                for (int s = 0; s < 5; ++s)
                    Xold[r * 5 + s] = X[(kbase + 2 * s) * DP + rb];
            }
        }

        /* ---- wait for all peer partials, update beliefs ---- */
        if (tid < S) {
            mbar_wait_parity(mbarAddr, (uint32_t)(it & 1));
            const float tot = -(myPart + sm[OFF_ACC + buf * S + tid]);
            sm[OFF_ACC + buf * S + tid] = 0.f;      /* re-arm for it+2 */
            sm[OFF_RS + tid] = 0.f;
            dbFinal = sm[OFF_SE + tid] + sm[OFF_MJ + tid] * tot;
            DB[tid] = dbFinal;
            EX[tid] = ex2f_(fminf(fmaxf(dbFinal, -30.f), 30.f));
        }
        __syncthreads();   /* DB/EX/RS/ACC ready; staging reads done pre-write */
    }

    /* ---- output: out[b, j, i, :] = softmax over channels (base-2) ---- */
    if (rank == 0 && tid < S) {
        const float Dv = dbFinal;
        const float e  = ex2f_(-fabsf(Dv));
        const float pb_ = 1.f / (1.f + e);
        const float ps = e * pb_;
        const float p1 = (Dv >= 0.f) ? pb_ : ps;
        const float p0 = (Dv >= 0.f) ? ps : pb_;
        float* o = out + ((size_t)((b * S + tid) * S + i)) * 2;
        o[0] = p0;
        o[1] = p1;
    }
}

extern "C" void kernel_launch(void* const* d_in, const int* in_sizes, int n_in,
                              void* d_out, int out_size) {
    (void)in_sizes; (void)n_in; (void)out_size;
    cudaFuncSetAttribute(lbp_kernel,
                         cudaFuncAttributeMaxDynamicSharedMemorySize, SMEM_BYTES);
    const float* s_edge = (const float*)d_in[0];
    const float* s_sib  = (const float*)d_in[1];
    const float* s_cop  = (const float*)d_in[2];
    const float* s_grd  = (const float*)d_in[3];
    const void*  mask   = d_in[4];
    float* outp = (float*)d_out;

    lbp_kernel<<<2 * S * 6, NTH, SMEM_BYTES>>>(
        s_edge, s_sib, s_cop, s_grd, mask, outp);
}

// round 14
// speedup vs baseline: 1.1511x; 1.1511x over previous
#include <cuda_runtime.h>
#include <cstdint>

// LBP semantic dependency, difference-space, ratio-space state X = 2^(-d).
// 6-CTA cluster per (i,b): rank -> (type t=r>>1, parity c=r&1).
// Pv = 2^(p*log2e) computed on it=0 from raw p, persisted to gmem scratch
// (L2-hot on it=1,2). Rowsums via smem atomics. Belief diffs are recomputed
// PER THREAD from double-buffered RS/ACC (no serialized DB phase, no EX
// array); one __syncthreads + one cluster.sync per iteration.

#define S    160
#define S2   25600
#define S3   4096000
#define DP   81          /* X pitch */
#define NTH  512
#define LOG2E 1.4426950408889634f

/* shared layout (floats) */
#define OFF_X    0                    /* X[160][81] = 12960 */
#define OFF_SE   12960
#define OFF_W    13120
#define OFF_MJ   13280
#define OFF_RS   13440                /* [2][160] local rowsum buffers */
#define OFF_ACC  13760                /* [2][160] peer partial buffers */
#define SMEM_FLOATS (OFF_ACC + 2*S)
#define SMEM_BYTES  (SMEM_FLOATS * 4)

/* global scratch for Pv: [b][i][rank][k(160)][jh(80)] = 98.3 MB */
__device__ float P2g[2 * 160 * 6 * 160 * 80];

extern __shared__ float sm[];

__device__ __forceinline__ uint32_t smem_u32(const void* p) {
    uint32_t a;
    asm("{ .reg .u64 t; cvta.to.shared.u64 t, %1; cvt.u32.u64 %0, t; }"
        : "=r"(a) : "l"(p));
    return a;
}
__device__ __forceinline__ void cluster_sync_() {
    asm volatile("barrier.cluster.arrive.aligned;" ::: "memory");
    asm volatile("barrier.cluster.wait.aligned;" ::: "memory");
}
__device__ __forceinline__ void red_remote_add_f32(uint32_t laddr, uint32_t rank, float v) {
    asm volatile(
        "{ .reg .b32 r; mapa.shared::cluster.u32 r, %0, %1; "
        "red.relaxed.cluster.shared::cluster.add.f32 [r], %2; }"
        :: "r"(laddr), "r"(rank), "f"(v) : "memory");
}
__device__ __forceinline__ float ex2f_(float x) {
    float y; asm("ex2.approx.ftz.f32 %0, %1;" : "=f"(y) : "f"(x)); return y;
}
__device__ __forceinline__ float lg2f_(float x) {
    float y; asm("lg2.approx.ftz.f32 %0, %1;" : "=f"(y) : "f"(x)); return y;
}
__device__ __forceinline__ float rcpf_(float x) {
    float y; asm("rcp.approx.ftz.f32 %0, %1;" : "=f"(y) : "f"(x)); return y;
}
__device__ __forceinline__ bool mask_at(const void* m, bool byteMask, int idx) {
    if (byteMask) return ((const unsigned char*)m)[idx] != 0;
    return ((const uint32_t*)m)[idx] != 0u;
}

__global__ void __launch_bounds__(NTH, 3) __cluster_dims__(6, 1, 1)
lbp_kernel(const float* __restrict__ s_edge,
           const float* __restrict__ s_sib,
           const float* __restrict__ s_cop,
           const float* __restrict__ s_grd,
           const void* __restrict__ mask,
           float* __restrict__ out)
{
    const int tid  = threadIdx.x;
    const int bx   = blockIdx.x;
    const int rank = bx % 6;
    const int prob = bx / 6;
    const int i    = prob % S;
    const int b    = prob / S;
    const int t    = rank >> 1;      /* score type */
    const int c    = rank & 1;       /* pair-parity class */

    const int tr    = tid & 31;              /* lane: row group */
    const int tc    = tid >> 5;              /* warp: col group */
    const int par   = c ^ (tr & 1);          /* fixed column parity */
    const int kbase = 10 * tc + par;         /* k_s = kbase + 2s */

    const bool byteMask = (*(const uint32_t*)mask == 0x01010101u);

    float* __restrict__ X   = sm + OFF_X;
    float* __restrict__ RS  = sm + OFF_RS;
    float* __restrict__ ACC = sm + OFF_ACC;

    const float* __restrict__ Praw =
        (t == 0 ? s_sib : (t == 1 ? s_cop : s_grd)) + (size_t)b * S3 + i * S;
    float* __restrict__ P2 = P2g + ((size_t)(b * S + i) * 6 + rank) * 12800;

    /* per-thread bases: raw p at [k][j], scratch at [k][jh] */
    const float* __restrict__ pb  = Praw + (size_t)kbase * S2 + tr;
    float*       __restrict__ p2b = P2 + kbase * 80 + (tr >> 1);

    /* ---- init scalars (X needs no init: it=0 writes every cell) ---- */
    if (tid < S) {
        const int k = tid;
        const bool mk = mask_at(mask, byteMask, b * S2 + k * S + i);
        sm[OFF_W  + k] = (mk && (k != i)) ? 1.f : 0.f;
        sm[OFF_MJ + k] = mk ? 1.f : 0.f;
        sm[OFF_SE + k] = s_edge[b * S2 + k * S + i] * LOG2E;
        RS[k] = 0.f;  RS[S + k] = 0.f;
        ACC[k] = 0.f; ACC[S + k] = 0.f;
    }
    __syncthreads();
    cluster_sync_();   /* all ranks' buffers zeroed before any remote red */

    const uint32_t accAddr = smem_u32(ACC);

    /* hoisted per-column weights (constant across iterations) */
    float Wreg[5];
    #pragma unroll
    for (int s = 0; s < 5; ++s) Wreg[s] = sm[OFF_W + kbase + 2 * s];

    float Xold[25];   /* transpose partners, staged at end of prev iteration */

    for (int it = 0; it < 3; ++it) {
        const int buf  = it & 1;
        const int pbuf = buf ^ 1;
        float acc[5];

        if (it == 0) {
            /* Xold = 1, E = 1 -> e = 1. Compute Pv from raw p; persist it. */
            #pragma unroll
            for (int r = 0; r < 5; ++r) {
                const int jv = tr + 32 * r;
                const int wrow = jv * DP + 5 * tc;
                float av = 0.f;
                #pragma unroll
                for (int s = 0; s < 5; ++s) {
                    const int k = kbase + 2 * s;
                    const float Pv = ex2f_(pb[(size_t)2 * s * S2 + 32 * r] * LOG2E);
                    p2b[160 * s + 16 * r] = Pv;
                    const float rr = 2.f * rcpf_(1.f + Pv);   /* 2^(-d_new) */
                    X[wrow + s] = rr;
                    const float dn = lg2f_(rr);               /* = -d_new */
                    const float wc = (k == jv) ? 0.f : Wreg[s];
                    av = fmaf(wc, dn, av);
                }
                acc[r] = av;
            }
        } else {
            /* per-thread belief-diff recompute (broadcast LDS, 5 ex2) */
            float Ereg[5];
            #pragma unroll
            for (int s = 0; s < 5; ++s) {
                const int k = kbase + 2 * s;
                const float tot = RS[pbuf * S + k] + ACC[pbuf * S + k];
                const float dbk = sm[OFF_SE + k] - sm[OFF_MJ + k] * tot;
                Ereg[s] = ex2f_(fminf(fmaxf(dbk, -30.f), 30.f));
            }

            #pragma unroll
            for (int r = 0; r < 5; ++r) {
                const int jv = tr + 32 * r;
                const int wrow = jv * DP + 5 * tc;
                float av = 0.f;
                #pragma unroll
                for (int s = 0; s < 5; ++s) {
                    const int k  = kbase + 2 * s;
                    const float Pv = p2b[160 * s + 16 * r];   /* L2-hot */
                    const float e  = Ereg[s] * Xold[r * 5 + s];
                    const float num = fmaf(e, Pv, 1.f);
                    const float den = e + 1.f;
                    const float rr  = den * rcpf_(num);       /* 2^(-d_new) */
                    X[wrow + s] = rr;
                    const float dn  = lg2f_(rr);              /* = -d_new */
                    const float wc  = (k == jv) ? 0.f : Wreg[s];
                    av = fmaf(wc, dn, av);
                }
                acc[r] = av;
            }
        }

        #pragma unroll
        for (int r = 0; r < 5; ++r)
            atomicAdd(&RS[buf * S + tr + 32 * r], acc[r]);
        __syncthreads();   /* X writes + RS[buf] complete; prev-buf reads done */

        /* ---- post partials to 5 peers; recycle previous buffers ---- */
        if (tid < S) {
            const float myPart = RS[buf * S + tid];
            const uint32_t dst = accAddr + 4u * (uint32_t)(buf * S + tid);
            #pragma unroll
            for (int r = 0; r < 6; ++r)
                if (r != rank) red_remote_add_f32(dst, (uint32_t)r, myPart);
            RS[pbuf * S + tid]  = 0.f;   /* re-arm for it+1's accumulation */
            ACC[pbuf * S + tid] = 0.f;
        }

        /* ---- stage next iter's transpose partners (hides rendezvous) ---- */
        if (it < 2) {
            #pragma unroll
            for (int r = 0; r < 5; ++r) {
                const int rb = (tr >> 1) + 16 * r;
                #pragma unroll
                for (int s = 0; s < 5; ++s)
                    Xold[r * 5 + s] = X[(kbase + 2 * s) * DP + rb];
            }
        }

        cluster_sync_();   /* peer partials landed; CTA barrier for X/RS/ACC */
    }

    /* ---- output: recompute final Δb; out[b, j, i, :] = softmax ---- */
    if (rank == 0 && tid < S) {
        const float tot = RS[tid] + ACC[tid];           /* buf of it=2 is 0 */
        const float Dv  = sm[OFF_SE + tid] - sm[OFF_MJ + tid] * tot;
        const float e   = ex2f_(-fabsf(Dv));
        const float pb_ = 1.f / (1.f + e);
        const float ps  = e * pb_;
        const float p1  = (Dv >= 0.f) ? pb_ : ps;
        const float p0  = (Dv >= 0.f) ? ps : pb_;
        float* o = out + ((size_t)((b * S + tid) * S + i)) * 2;
        o[0] = p0;
        o[1] = p1;
    }
}

extern "C" void kernel_launch(void* const* d_in, const int* in_sizes, int n_in,
                              void* d_out, int out_size) {
    (void)in_sizes; (void)n_in; (void)out_size;
    cudaFuncSetAttribute(lbp_kernel,
                         cudaFuncAttributeMaxDynamicSharedMemorySize, SMEM_BYTES);
    const float* s_edge = (const float*)d_in[0];
    const float* s_sib  = (const float*)d_in[1];
    const float* s_cop  = (const float*)d_in[2];
    const float* s_grd  = (const float*)d_in[3];
    const void*  mask   = d_in[4];
    float* outp = (float*)d_out;

    lbp_kernel<<<2 * S * 6, NTH, SMEM_BYTES>>>(
        s_edge, s_sib, s_cop, s_grd, mask, outp);
}

// round 15
// speedup vs baseline: 1.4298x; 1.2421x over previous
#include <cuda_runtime.h>
#include <cstdint>

// LBP semantic dependency, difference-space, ratio-space state X = 2^(-d).
// 6-CTA cluster per (i,b): rank -> (type t=r>>1, parity c=r&1).
// Pv = 2^(p*log2e) computed on it=0 from raw p and persisted to gmem scratch
// (L2-hot on it=1,2). Rowsums in PRODUCT domain: prod *= (sel ? rr : 1),
// one lg2 per 5-cell group (40% MUFU cut vs per-cell lg2). Otherwise = R10.

#define S    160
#define S2   25600
#define S3   4096000
#define DP   81          /* X pitch */
#define NTH  512
#define LOG2E 1.4426950408889634f

/* shared layout (floats) */
#define OFF_X    0                    /* X[160][81] = 12960 */
#define OFF_DB   12960
#define OFF_SE   13120
#define OFF_W    13280
#define OFF_MJ   13440
#define OFF_RS   13600
#define OFF_ACC  13760                /* [2][160] */
#define OFF_EX   14080
#define SMEM_FLOATS (OFF_EX + S)
#define SMEM_BYTES  (SMEM_FLOATS * 4)

/* global scratch for Pv: [b][i][rank][k(160)][jh(80)] = 98.3 MB */
__device__ float P2g[2 * 160 * 6 * 160 * 80];

extern __shared__ float sm[];

__device__ __forceinline__ uint32_t smem_u32(const void* p) {
    uint32_t a;
    asm("{ .reg .u64 t; cvta.to.shared.u64 t, %1; cvt.u32.u64 %0, t; }"
        : "=r"(a) : "l"(p));
    return a;
}
__device__ __forceinline__ void cluster_sync_() {
    asm volatile("barrier.cluster.arrive.aligned;" ::: "memory");
    asm volatile("barrier.cluster.wait.aligned;" ::: "memory");
}
__device__ __forceinline__ void red_remote_add_f32(uint32_t laddr, uint32_t rank, float v) {
    asm volatile(
        "{ .reg .b32 r; mapa.shared::cluster.u32 r, %0, %1; "
        "red.relaxed.cluster.shared::cluster.add.f32 [r], %2; }"
        :: "r"(laddr), "r"(rank), "f"(v) : "memory");
}
__device__ __forceinline__ float ex2f_(float x) {
    float y; asm("ex2.approx.ftz.f32 %0, %1;" : "=f"(y) : "f"(x)); return y;
}
__device__ __forceinline__ float lg2f_(float x) {
    float y; asm("lg2.approx.ftz.f32 %0, %1;" : "=f"(y) : "f"(x)); return y;
}
__device__ __forceinline__ float rcpf_(float x) {
    float y; asm("rcp.approx.ftz.f32 %0, %1;" : "=f"(y) : "f"(x)); return y;
}
__device__ __forceinline__ bool mask_at(const void* m, bool byteMask, int idx) {
    if (byteMask) return ((const unsigned char*)m)[idx] != 0;
    return ((const uint32_t*)m)[idx] != 0u;
}

__global__ void __launch_bounds__(NTH, 3) __cluster_dims__(6, 1, 1)
lbp_kernel(const float* __restrict__ s_edge,
           const float* __restrict__ s_sib,
           const float* __restrict__ s_cop,
           const float* __restrict__ s_grd,
           const void* __restrict__ mask,
           float* __restrict__ out)
{
    const int tid  = threadIdx.x;
    const int bx   = blockIdx.x;
    const int rank = bx % 6;
    const int prob = bx / 6;
    const int i    = prob % S;
    const int b    = prob / S;
    const int t    = rank >> 1;      /* score type */
    const int c    = rank & 1;       /* pair-parity class */

    const int tr    = tid & 31;              /* lane: row group */
    const int tc    = tid >> 5;              /* warp: col group */
    const int par   = c ^ (tr & 1);          /* fixed column parity */
    const int kbase = 10 * tc + par;         /* k_s = kbase + 2s */

    const bool byteMask = (*(const uint32_t*)mask == 0x01010101u);

    float* __restrict__ X  = sm + OFF_X;
    float* __restrict__ DB = sm + OFF_DB;
    float* __restrict__ EX = sm + OFF_EX;

    const float* __restrict__ Praw =
        (t == 0 ? s_sib : (t == 1 ? s_cop : s_grd)) + (size_t)b * S3 + i * S;
    float* __restrict__ P2 = P2g + ((size_t)(b * S + i) * 6 + rank) * 12800;

    /* per-thread bases: raw p at [k][j], scratch at [k][jh] */
    const float* __restrict__ pb  = Praw + (size_t)kbase * S2 + tr;
    float*       __restrict__ p2b = P2 + kbase * 80 + (tr >> 1);

    /* ---- init scalars (X needs no init: it=0 writes every cell) ---- */
    if (tid < S) {
        const int k = tid;
        const bool mk = mask_at(mask, byteMask, b * S2 + k * S + i);
        sm[OFF_W  + k] = (mk && (k != i)) ? 1.f : 0.f;
        sm[OFF_MJ + k] = mk ? 1.f : 0.f;
        sm[OFF_SE + k] = s_edge[b * S2 + k * S + i] * LOG2E;
        DB[k] = 0.f;
        EX[k] = 1.f;
        sm[OFF_RS + k] = 0.f;
        sm[OFF_ACC + k] = 0.f;
        sm[OFF_ACC + S + k] = 0.f;
    }
    __syncthreads();
    cluster_sync_();   /* all ranks' ACC zeroed before any remote red */

    const uint32_t accAddr = smem_u32(sm + OFF_ACC);
    float dbFinal = 0.f;

    /* hoisted per-column weights (constant across iterations) */
    float Wreg[5];
    #pragma unroll
    for (int s = 0; s < 5; ++s) Wreg[s] = sm[OFF_W + kbase + 2 * s];

    for (int it = 0; it < 3; ++it) {
        float acc[5];

        if (it == 0) {
            /* Xold = 1, E = 1 -> e = 1. Compute Pv from raw p; persist it. */
            #pragma unroll
            for (int r = 0; r < 5; ++r) {
                const int jv = tr + 32 * r;
                const int wrow = jv * DP + 5 * tc;
                float prod = 1.f;
                #pragma unroll
                for (int s = 0; s < 5; ++s) {
                    const int k = kbase + 2 * s;
                    const float Pv = ex2f_(pb[(size_t)2 * s * S2 + 32 * r] * LOG2E);
                    p2b[160 * s + 16 * r] = Pv;
                    const float rr = 2.f * rcpf_(1.f + Pv);   /* 2^(-d_new) */
                    X[wrow + s] = rr;
                    const float rsel = (k != jv && Wreg[s] != 0.f) ? rr : 1.f;
                    prod *= rsel;
                }
                acc[r] = lg2f_(prod);       /* = sum w * (-d_new) over cols */
            }
        } else {
            /* stage transpose partners X_old[k][jv] into regs */
            float Xold[25];
            #pragma unroll
            for (int r = 0; r < 5; ++r) {
                const int rb = (tr >> 1) + 16 * r;
                #pragma unroll
                for (int s = 0; s < 5; ++s)
                    Xold[r * 5 + s] = X[(kbase + 2 * s) * DP + rb];
            }
            __syncthreads();   /* all reads before any writes */

            float Ereg[5];
            #pragma unroll
            for (int s = 0; s < 5; ++s) Ereg[s] = EX[kbase + 2 * s];

            #pragma unroll
            for (int r = 0; r < 5; ++r) {
                const int jv = tr + 32 * r;
                const int wrow = jv * DP + 5 * tc;
                float prod = 1.f;
                #pragma unroll
                for (int s = 0; s < 5; ++s) {
                    const int k  = kbase + 2 * s;
                    const float Pv = p2b[160 * s + 16 * r];   /* L2-hot */
                    const float e  = Ereg[s] * Xold[r * 5 + s];
                    const float num = fmaf(e, Pv, 1.f);
                    const float den = e + 1.f;
                    const float rr  = den * rcpf_(num);       /* 2^(-d_new) */
                    X[wrow + s] = rr;
                    const float rsel = (k != jv && Wreg[s] != 0.f) ? rr : 1.f;
                    prod *= rsel;
                }
                acc[r] = lg2f_(prod);
            }
        }

        #pragma unroll
        for (int r = 0; r < 5; ++r)
            atomicAdd(&sm[OFF_RS + tr + 32 * r], acc[r]);
        __syncthreads();   /* X writes + RS complete */

        /* ---- Δb all-reduce across the 6 ranks (RS holds -rowsum) ---- */
        const int buf = it & 1;
        float myPart = 0.f;
        if (tid < S) {
            myPart = sm[OFF_RS + tid];
            const uint32_t dst = accAddr + 4u * (uint32_t)(buf * S + tid);
            #pragma unroll
            for (int r = 0; r < 6; ++r)
                if (r != rank) red_remote_add_f32(dst, (uint32_t)r, myPart);
        }
        cluster_sync_();   /* peer partials landed */
        if (tid < S) {
            const float tot = -(myPart + sm[OFF_ACC + buf * S + tid]);
            sm[OFF_ACC + buf * S + tid] = 0.f;      /* re-arm for it+2 */
            sm[OFF_RS + tid] = 0.f;
            dbFinal = sm[OFF_SE + tid] + sm[OFF_MJ + tid] * tot;
            DB[tid] = dbFinal;
            EX[tid] = ex2f_(fminf(fmaxf(dbFinal, -30.f), 30.f));
        }
        /* next iter's stage __syncthreads orders DB/EX/RS/ACC for all */
    }

    /* ---- output: out[b, j, i, :] = softmax over channels (base-2) ---- */
    if (rank == 0 && tid < S) {
        const float Dv = dbFinal;
        const float e  = ex2f_(-fabsf(Dv));
        const float pb_ = 1.f / (1.f + e);
        const float ps = e * pb_;
        const float p1 = (Dv >= 0.f) ? pb_ : ps;
        const float p0 = (Dv >= 0.f) ? ps : pb_;
        float* o = out + ((size_t)((b * S + tid) * S + i)) * 2;
        o[0] = p0;
        o[1] = p1;
    }
}

extern "C" void kernel_launch(void* const* d_in, const int* in_sizes, int n_in,
                              void* d_out, int out_size) {
    (void)in_sizes; (void)n_in; (void)out_size;
    cudaFuncSetAttribute(lbp_kernel,
                         cudaFuncAttributeMaxDynamicSharedMemorySize, SMEM_BYTES);
    const float* s_edge = (const float*)d_in[0];
    const float* s_sib  = (const float*)d_in[1];
    const float* s_cop  = (const float*)d_in[2];
    const float* s_grd  = (const float*)d_in[3];
    const void*  mask   = d_in[4];
    float* outp = (float*)d_out;

    lbp_kernel<<<2 * S * 6, NTH, SMEM_BYTES>>>(
        s_edge, s_sib, s_cop, s_grd, mask, outp);
}